// round 16
// baseline (speedup 1.0000x reference)
#include <cuda_runtime.h>
#include <cstdint>
#include <cstddef>

#define NTHR 512
#define TB 4
#define NBLK 512   // 2048 / TB

// transposed weights in device globals (written by k_tr each launch)
__device__ float gWT[3][16384];     // gWT[l][t*128+k] = Wh[l][k*128+t]
__device__ float gWiT[128 * 132];   // gWiT[t*132+j]   = Wi[j*128+t]  (j<131)

__global__ void k_tr(const float* __restrict__ Wh, const float* __restrict__ Wi)
{
    int gt = blockIdx.x * 256 + threadIdx.x;
    if (gt < 3 * 16384) {
        int l = gt >> 14, r = gt & 16383, a = r >> 7, b = r & 127;
        gWT[l][r] = Wh[(l << 14) + b * 128 + a];
    } else {
        int g2 = gt - 3 * 16384;
        if (g2 < 128 * 131) {
            int t = g2 / 131, j = g2 % 131;
            gWiT[t * 132 + j] = Wi[j * 128 + t];
        }
    }
}

// zero example e's d2f row (4096 float4), skipping the first float4
#define ZCHUNK(e_) do {                                                         \
    float4 z4 = make_float4(0.f, 0.f, 0.f, 0.f);                                \
    float4* dst_ = (float4*)(o_d2f + (size_t)(b0 + (e_)) * 16384);              \
    for (int i_ = 1 + tid; i_ < 4096; i_ += NTHR) __stcs(dst_ + i_, z4);        \
  } while (0)

// split-K partial GEMV: acc over k in [K0,K1)
#define GEMVPART(WCOL, PITCHW, ACT, K0, K1, A0, A1, A2, A3) do {                \
    _Pragma("unroll 8")                                                         \
    for (int k = (K0); k < (K1); k++) {                                         \
        float w = __ldg((WCOL) + k * (PITCHW) + t);                             \
        float4 hv = *(const float4*)((ACT) + k * 4);                            \
        A0 = fmaf(w, hv.x, A0);                                                 \
        A1 = fmaf(w, hv.y, A1);                                                 \
        A2 = fmaf(w, hv.z, A2);                                                 \
        A3 = fmaf(w, hv.w, A3);                                                 \
    }                                                                           \
  } while (0)

// combine 4 split-K partials for slot t (called by kq==0 threads)
#define COMBINE4(OUTX, OUTY, OUTZ, OUTW) \
    float4 p0_ = *(const float4*)(Ps + 0 * 512 + t * 4);                        \
    float4 p1_ = *(const float4*)(Ps + 1 * 512 + t * 4);                        \
    float4 p2_ = *(const float4*)(Ps + 2 * 512 + t * 4);                        \
    float4 p3_ = *(const float4*)(Ps + 3 * 512 + t * 4);                        \
    float OUTX = (p0_.x + p1_.x) + (p2_.x + p3_.x);                             \
    float OUTY = (p0_.y + p1_.y) + (p2_.y + p3_.y);                             \
    float OUTZ = (p0_.z + p1_.z) + (p2_.z + p3_.z);                             \
    float OUTW = (p0_.w + p1_.w) + (p2_.w + p3_.w);

__global__ void __launch_bounds__(NTHR, 3)
fused_kernel(const float* __restrict__ centers,
             const float* __restrict__ eps,
             const float* __restrict__ dk,
             const float* __restrict__ Wi,
             const float* __restrict__ Wh,
             const float* __restrict__ bh,
             const float* __restrict__ bf,
             const void* __restrict__ pA2048, const void* __restrict__ pB2048,
             const float* __restrict__ pA128, const float* __restrict__ pB128,
             float* __restrict__ o_res, float* __restrict__ o_fmean,
             float* __restrict__ o_flog, float* __restrict__ o_coeffs,
             float* __restrict__ o_d1c, float* __restrict__ o_d2c,
             float* __restrict__ o_d1o, float* __restrict__ o_d2o,
             float* __restrict__ o_d1f, float* __restrict__ o_d2f)
{
    __shared__ float Xst[528];        // input vectors [k][e], 131 rows
    __shared__ float Hst[3 * 512];    // h1,h2,h3 as [t][e]  (relu'd, = masks)
    __shared__ float Ua[512];         // backward ping [t][e]
    __shared__ float Ub[512];         // backward pong [t][e]
    __shared__ float Ps[4 * 512];     // split-K partials [kq][t][e]
    __shared__ float valP[16];        // per-warp val partials [w][e] (warps 0..3)
    __shared__ float sS[TB], cS[TB], xsS[TB];
    __shared__ int   idxS[TB];

    const int tid = threadIdx.x;
    const int t  = tid & 127;          // neuron / output index
    const int kq = tid >> 7;           // k-quarter 0..3
    const int wid = tid >> 5;
    const int lane = tid & 31;
    const int b0 = blockIdx.x * TB;

    // --- resolve ambiguous inputs ---
    const unsigned* ua_ = (const unsigned*)pA2048;
    bool a_idx = true;
#pragma unroll
    for (int i = 0; i < 8; i++) a_idx &= (ua_[i] < 1000u);
    const int*   idxp = (const int*)(a_idx ? pA2048 : pB2048);
    const float* xsp  = (const float*)(a_idx ? pB2048 : pA2048);
    bool a_bi = true;
#pragma unroll
    for (int i = 0; i < 8; i++) a_bi &= (pA128[i] == 0.0f);
    const float* bi = a_bi ? pA128 : pB128;
    const float* Wf = a_bi ? pB128 : pA128;

    // --- phase 0a ---
    if (tid < TB) {
        int gb = b0 + tid;
        idxS[tid] = idxp[gb];
        cS[tid]   = centers[gb * 4];
        Xst[1 * 4 + tid] = centers[gb * 4 + 1];
        Xst[2 * 4 + tid] = centers[gb * 4 + 2];
        Xst[3 * 4 + tid] = centers[gb * 4 + 3];
        xsS[tid]  = xsp[gb];
    }
    __syncthreads();

    // --- phase 0b: gather feat (transposed), write fmean/flog ---
    {
        int b = kq >> 1;               // wrong mapping? use e2 decomposition
        // one element per thread: e2 = tid covers TB*128 = 512 items
        int e2 = tid;
        b = e2 >> 7;
        int k = e2 & 127;
        int gb = b0 + b;
        int id = idxS[b];
        float m  = dk[id * 256 + k];
        float ls = dk[id * 256 + 128 + k];
        float ep = eps[id * 128 + k];
        float ft = fmaf(expf(0.5f * ls), ep, m);
        o_fmean[(size_t)gb * 128 + k] = m;
        o_flog[(size_t)gb * 128 + k]  = ls;
        if (k == 0) {
            float s = 1e-10f + expf(-ft);
            sS[b] = s;
            Xst[b] = cS[b] * s;
        } else {
            Xst[(3 + k) * 4 + b] = ft;
        }
    }
    __syncthreads();
    ZCHUNK(0);

    // --- L1: partials over j quarters of [0,131) : 33/33/33/32 ---
    {
        float a0, a1, a2, a3;
        if (kq == 0) { float bv = bi[t]; a0 = a1 = a2 = a3 = bv; }
        else         { a0 = a1 = a2 = a3 = 0.f; }
        int j0 = kq * 33;
        int j1 = (kq == 3) ? 131 : (j0 + 33);
        GEMVPART(Wi, 128, Xst, j0, j1, a0, a1, a2, a3);
        *(float4*)(Ps + kq * 512 + t * 4) = make_float4(a0, a1, a2, a3);
    }
    __syncthreads();
    if (kq == 0) {
        COMBINE4(a0, a1, a2, a3);
        *(float4*)(Hst + t * 4) = make_float4(
            fmaxf(a0, 0.f), fmaxf(a1, 0.f), fmaxf(a2, 0.f), fmaxf(a3, 0.f));
    }
    __syncthreads();

    // --- L2, L3 ---
#pragma unroll
    for (int l = 0; l < 2; l++) {
        float a0, a1, a2, a3;
        if (kq == 0) { float bv = bh[l * 128 + t]; a0 = a1 = a2 = a3 = bv; }
        else         { a0 = a1 = a2 = a3 = 0.f; }
        GEMVPART(Wh + l * 16384, 128, Hst + l * 512, kq * 32, kq * 32 + 32, a0, a1, a2, a3);
        *(float4*)(Ps + kq * 512 + t * 4) = make_float4(a0, a1, a2, a3);
        __syncthreads();
        if (kq == 0) {
            COMBINE4(c0, c1, c2, c3);
            *(float4*)(Hst + (l + 1) * 512 + t * 4) = make_float4(
                fmaxf(c0, 0.f), fmaxf(c1, 0.f), fmaxf(c2, 0.f), fmaxf(c3, 0.f));
        }
        __syncthreads();
        if (l == 0) ZCHUNK(1);
    }

    // --- L4 + val partials + u4 init (h4 never stored) ---
    {
        float a0, a1, a2, a3;
        if (kq == 0) { float bv = bh[2 * 128 + t]; a0 = a1 = a2 = a3 = bv; }
        else         { a0 = a1 = a2 = a3 = 0.f; }
        GEMVPART(Wh + 2 * 16384, 128, Hst + 2 * 512, kq * 32, kq * 32 + 32, a0, a1, a2, a3);
        *(float4*)(Ps + kq * 512 + t * 4) = make_float4(a0, a1, a2, a3);
    }
    __syncthreads();
    if (kq == 0) {
        COMBINE4(a0, a1, a2, a3);
        float wf_t = Wf[t];
        float4 ov;
        ov.x = (a0 > 0.f) ? wf_t : 0.f;
        ov.y = (a1 > 0.f) ? wf_t : 0.f;
        ov.z = (a2 > 0.f) ? wf_t : 0.f;
        ov.w = (a3 > 0.f) ? wf_t : 0.f;
        *(float4*)(Ua + t * 4) = ov;

        float q0 = fmaxf(a0, 0.f) * wf_t;
        float q1 = fmaxf(a1, 0.f) * wf_t;
        float q2 = fmaxf(a2, 0.f) * wf_t;
        float q3 = fmaxf(a3, 0.f) * wf_t;
#pragma unroll
        for (int o = 16; o > 0; o >>= 1) {
            q0 += __shfl_down_sync(0xffffffffu, q0, o);
            q1 += __shfl_down_sync(0xffffffffu, q1, o);
            q2 += __shfl_down_sync(0xffffffffu, q2, o);
            q3 += __shfl_down_sync(0xffffffffu, q3, o);
        }
        if (lane == 0) *(float4*)(valP + wid * 4) = make_float4(q0, q1, q2, q3);
    }
    __syncthreads();
    ZCHUNK(2);

    // --- backward: B3 (Wh2^T), B2 (Wh1^T), B1 (Wh0^T) — split-K partials ---
#pragma unroll
    for (int s = 0; s < 3; s++) {
        const float* WT = gWT[2 - s];
        const float* Uin  = (s == 1) ? Ub : Ua;   // B3: Ua->Ub, B2: Ub->Ua, B1: Ua->Ub
        float*       Uout = (s == 1) ? Ua : Ub;
        const float* Hm = Hst + (2 - s) * 512;
        float a0 = 0.f, a1 = 0.f, a2 = 0.f, a3 = 0.f;
        GEMVPART(WT, 128, Uin, kq * 32, kq * 32 + 32, a0, a1, a2, a3);
        *(float4*)(Ps + kq * 512 + t * 4) = make_float4(a0, a1, a2, a3);
        __syncthreads();
        if (kq == 0) {
            COMBINE4(c0, c1, c2, c3);
            float4 hm = *(const float4*)(Hm + t * 4);
            float4 ov;
            ov.x = (hm.x > 0.f) ? c0 : 0.f;
            ov.y = (hm.y > 0.f) ? c1 : 0.f;
            ov.z = (hm.z > 0.f) ? c2 : 0.f;
            ov.w = (hm.w > 0.f) ? c3 : 0.f;
            *(float4*)(Uout + t * 4) = ov;
        }
        __syncthreads();
        if (s == 0) ZCHUNK(3);
    }

    // --- final: g[j] = sum_k WiT[k*132+j] * u1[k]; u1 in Ub ---
    {
        int j = t;
        float g0 = 0.f, g1 = 0.f, g2 = 0.f, g3 = 0.f;
#pragma unroll 8
        for (int k = kq * 32; k < kq * 32 + 32; k++) {
            float w = __ldg(gWiT + k * 132 + j);
            float4 uv = *(const float4*)(Ub + k * 4);
            g0 = fmaf(w, uv.x, g0);
            g1 = fmaf(w, uv.y, g1);
            g2 = fmaf(w, uv.z, g2);
            g3 = fmaf(w, uv.w, g3);
        }
        *(float4*)(Ps + kq * 512 + t * 4) = make_float4(g0, g1, g2, g3);
    }
    __syncthreads();

    if (kq == 0) {
        int j = t;
        COMBINE4(c0, c1, c2, c3);
        float g[4] = {c0, c1, c2, c3};

        if (j >= 4) {
#pragma unroll
            for (int e = 0; e < TB; e++) {
                int gb = b0 + e;
                o_d1f[(size_t)gb * 128 + (j - 3)] = g[e];
            }
        } else if (j == 0) {
#pragma unroll
            for (int e = 0; e < TB; e++) {
                int gb = b0 + e;
                float val = valP[0 * 4 + e] + valP[1 * 4 + e]
                          + valP[2 * 4 + e] + valP[3 * 4 + e] + bf[0];
                float s = sS[e], c = cS[e];
                float gg = g[e];
                float d1c = gg * s;
                float h00 = gg * c * (s - 1e-10f);   // g0 * c * exp(-ft0)
                o_d1c[gb] = d1c;
                o_d2c[gb] = 0.f;
                o_coeffs[gb] = val;
                o_res[gb] = fmaf(d1c, xsS[e] - c, val);
                o_d1f[(size_t)gb * 128] = -h00;
                *(float4*)(o_d2f + (size_t)gb * 16384) = make_float4(h00, 0.f, 0.f, 0.f);
            }
        } else {  // j = 1..3
#pragma unroll
            for (int e = 0; e < TB; e++) {
                int gb = b0 + e;
                o_d1o[(size_t)gb * 3 + (j - 1)] = g[e];
            }
        }
    } else if (kq == 1 && t < 3) {
        // extra input rows j=128..130 -> d1f[125..127], quarter-1 in parallel
        int j2 = 128 + t;
        float q0 = 0.f, q1 = 0.f, q2 = 0.f, q3 = 0.f;
#pragma unroll 8
        for (int k = 0; k < 128; k++) {
            float w = __ldg(gWiT + k * 132 + j2);
            float4 uv = *(const float4*)(Ub + k * 4);
            q0 = fmaf(w, uv.x, q0);
            q1 = fmaf(w, uv.y, q1);
            q2 = fmaf(w, uv.z, q2);
            q3 = fmaf(w, uv.w, q3);
        }
        float qe[4] = {q0, q1, q2, q3};
#pragma unroll
        for (int e = 0; e < TB; e++) {
            int gb = b0 + e;
            o_d1f[(size_t)gb * 128 + 125 + t] = qe[e];
        }
    } else if (kq == 2 && t < TB * 9) {
        // d2o zeros (4 examples x 9), quarter-2 in parallel
        int b = t / 9, k9 = t % 9;
        o_d2o[(size_t)(b0 + b) * 9 + k9] = 0.f;
    }
}

extern "C" void kernel_launch(void* const* d_in, const int* in_sizes, int n_in,
                              void* d_out, int out_size)
{
    (void)out_size;
    const float *centers = 0, *eps = 0, *dk = 0, *Wi = 0, *Wh = 0, *bh = 0, *bf = 0;
    const void* p2048[2] = {0, 0};
    const float* p128[2] = {0, 0};
    int n2 = 0, n1 = 0;
    for (int i = 0; i < n_in; i++) {
        switch (in_sizes[i]) {
            case 8192:   centers = (const float*)d_in[i]; break;  // (2048,4)
            case 128000: eps     = (const float*)d_in[i]; break;  // (1000,128)
            case 256000: dk      = (const float*)d_in[i]; break;  // (1000,256)
            case 16768:  Wi      = (const float*)d_in[i]; break;  // (131,128)
            case 49152:  Wh      = (const float*)d_in[i]; break;  // (3,128,128)
            case 384:    bh      = (const float*)d_in[i]; break;  // (3,128)
            case 1:      bf      = (const float*)d_in[i]; break;  // (1,)
            case 2048:   if (n2 < 2) p2048[n2++] = d_in[i]; break; // indecies / xs
            case 128:    if (n1 < 2) p128[n1++] = (const float*)d_in[i]; break; // bi / Wf
            default: break;
        }
    }
    const int B = 2048;
    float* out = (float*)d_out;
    float* o_res    = out;
    float* o_fmean  = out + B;
    float* o_flog   = o_fmean + (size_t)B * 128;
    float* o_coeffs = o_flog + (size_t)B * 128;
    float* o_d1c    = o_coeffs + B;
    float* o_d2c    = o_d1c + B;
    float* o_d1o    = o_d2c + B;
    float* o_d2o    = o_d1o + (size_t)B * 3;
    float* o_d1f    = o_d2o + (size_t)B * 9;
    float* o_d2f    = o_d1f + (size_t)B * 128;

    k_tr<<<258, 256>>>(Wh, Wi);
    fused_kernel<<<NBLK, NTHR>>>(
        centers, eps, dk, Wi, Wh, bh, bf,
        p2048[0], p2048[1], p128[0], p128[1],
        o_res, o_fmean, o_flog, o_coeffs, o_d1c, o_d2c, o_d1o, o_d2o, o_d1f, o_d2f);
}

// round 17
// speedup vs baseline: 1.2521x; 1.2521x over previous
#include <cuda_runtime.h>
#include <cstdint>
#include <cstddef>

#define NTHR 256
#define TB 4
#define NBLK 512   // 2048 / TB

// Packed weights, written once per launch by k_pack.
// 8 matrices of 16384 floats, layout [k4][t][4] (float4 per (k4,t)):
//  m0    : forward Wi  rows 0..127   Wi[k*128+t]
//  m1..3 : forward Wh_l              Wh[l][k*128+t]
//  m4..6 : backward Wh_l^T           Wh[l][t*128+k]
//  m7    : final Wi^T (j=t dim)      Wi[j*128+k]
__device__ float gPK[8 * 16384];

__global__ void k_pack(const float* __restrict__ Wh, const float* __restrict__ Wi)
{
    int gt = blockIdx.x * 256 + threadIdx.x;   // 0..131071
    int m  = gt >> 14;
    int r  = gt & 16383;
    int k4 = r >> 9;
    int rem = r & 511;
    int t  = rem >> 2;
    int kk = rem & 3;
    int k  = k4 * 4 + kk;
    float v;
    if (m == 0)      v = Wi[k * 128 + t];
    else if (m <= 3) v = Wh[(m - 1) * 16384 + k * 128 + t];
    else if (m <= 6) v = Wh[(m - 4) * 16384 + t * 128 + k];
    else             v = Wi[t * 128 + k];
    gPK[gt] = v;
}

// zero example e's d2f row (4096 float4), skipping the first float4
#define ZCHUNK(e_) do {                                                         \
    float4 z4 = make_float4(0.f, 0.f, 0.f, 0.f);                                \
    float4* dst_ = (float4*)(o_d2f + (size_t)(b0 + (e_)) * 16384);              \
    for (int i_ = 1 + tid; i_ < 4096; i_ += NTHR) __stcs(dst_ + i_, z4);        \
  } while (0)

// packed split-K partial GEMV: acc over k4 in [K40,K41); PW = packed matrix base
#define GEMVP(PW, ACT, K40, K41, A0, A1, A2, A3) do {                           \
    _Pragma("unroll 4")                                                         \
    for (int k4 = (K40); k4 < (K41); k4++) {                                    \
        float4 wv = __ldg((const float4*)(PW) + k4 * 128 + t);                  \
        const float* ap_ = (ACT) + k4 * 16;                                     \
        float4 h_;                                                              \
        h_ = *(const float4*)(ap_);                                             \
        A0 = fmaf(wv.x, h_.x, A0); A1 = fmaf(wv.x, h_.y, A1);                   \
        A2 = fmaf(wv.x, h_.z, A2); A3 = fmaf(wv.x, h_.w, A3);                   \
        h_ = *(const float4*)(ap_ + 4);                                         \
        A0 = fmaf(wv.y, h_.x, A0); A1 = fmaf(wv.y, h_.y, A1);                   \
        A2 = fmaf(wv.y, h_.z, A2); A3 = fmaf(wv.y, h_.w, A3);                   \
        h_ = *(const float4*)(ap_ + 8);                                         \
        A0 = fmaf(wv.z, h_.x, A0); A1 = fmaf(wv.z, h_.y, A1);                   \
        A2 = fmaf(wv.z, h_.z, A2); A3 = fmaf(wv.z, h_.w, A3);                   \
        h_ = *(const float4*)(ap_ + 12);                                        \
        A0 = fmaf(wv.w, h_.x, A0); A1 = fmaf(wv.w, h_.y, A1);                   \
        A2 = fmaf(wv.w, h_.z, A2); A3 = fmaf(wv.w, h_.w, A3);                   \
    }                                                                           \
  } while (0)

__global__ void __launch_bounds__(NTHR)
fused_kernel(const float* __restrict__ centers,
             const float* __restrict__ eps,
             const float* __restrict__ dk,
             const float* __restrict__ Wi,
             const float* __restrict__ Wh,
             const float* __restrict__ bh,
             const float* __restrict__ bf,
             const void* __restrict__ pA2048, const void* __restrict__ pB2048,
             const float* __restrict__ pA128, const float* __restrict__ pB128,
             float* __restrict__ o_res, float* __restrict__ o_fmean,
             float* __restrict__ o_flog, float* __restrict__ o_coeffs,
             float* __restrict__ o_d1c, float* __restrict__ o_d2c,
             float* __restrict__ o_d1o, float* __restrict__ o_d2o,
             float* __restrict__ o_d1f, float* __restrict__ o_d2f)
{
    __shared__ float Xst[528];        // input vectors [k][e], 131 rows
    __shared__ float Hst[3 * 512];    // h1,h2,h3 as [t][e]  (relu'd, = masks)
    __shared__ float Ua[512];         // backward ping [t][e]
    __shared__ float Ub[512];         // backward pong [t][e]
    __shared__ float Ps[2 * 512];     // split-K partials [kh][t][e]
    __shared__ float valP[16];        // per-warp val partials [w][e]
    __shared__ float sS[TB], cS[TB], xsS[TB];
    __shared__ int   idxS[TB];

    const int tid = threadIdx.x;
    const int t  = tid & 127;          // neuron / output index
    const int kh = tid >> 7;           // k-half 0/1
    const int wid = tid >> 5;
    const int lane = tid & 31;
    const int b0 = blockIdx.x * TB;

    // --- resolve ambiguous inputs ---
    const unsigned* ua_ = (const unsigned*)pA2048;
    bool a_idx = true;
#pragma unroll
    for (int i = 0; i < 8; i++) a_idx &= (ua_[i] < 1000u);
    const int*   idxp = (const int*)(a_idx ? pA2048 : pB2048);
    const float* xsp  = (const float*)(a_idx ? pB2048 : pA2048);
    bool a_bi = true;
#pragma unroll
    for (int i = 0; i < 8; i++) a_bi &= (pA128[i] == 0.0f);
    const float* bi = a_bi ? pA128 : pB128;
    const float* Wf = a_bi ? pB128 : pA128;

    // --- phase 0a ---
    if (tid < TB) {
        int gb = b0 + tid;
        idxS[tid] = idxp[gb];
        cS[tid]   = centers[gb * 4];
        Xst[1 * 4 + tid] = centers[gb * 4 + 1];
        Xst[2 * 4 + tid] = centers[gb * 4 + 2];
        Xst[3 * 4 + tid] = centers[gb * 4 + 3];
        xsS[tid]  = xsp[gb];
    }
    __syncthreads();

    // --- phase 0b: gather feat (transposed), write fmean/flog ---
#pragma unroll
    for (int ii = 0; ii < 2; ii++) {
        int e2 = tid + NTHR * ii;
        int b = e2 >> 7;
        int k = e2 & 127;
        int gb = b0 + b;
        int id = idxS[b];
        float m  = dk[id * 256 + k];
        float ls = dk[id * 256 + 128 + k];
        float ep = eps[id * 128 + k];
        float ft = fmaf(expf(0.5f * ls), ep, m);
        o_fmean[(size_t)gb * 128 + k] = m;
        o_flog[(size_t)gb * 128 + k]  = ls;
        if (k == 0) {
            float s = 1e-10f + expf(-ft);
            sS[b] = s;
            Xst[b] = cS[b] * s;
        } else {
            Xst[(3 + k) * 4 + b] = ft;
        }
    }
    __syncthreads();
    ZCHUNK(0);

    // --- L1: packed partials; kh0: j4 0..16, kh1: j4 16..32 + rows 128..130 ---
    {
        float a0, a1, a2, a3;
        if (kh == 0) { float bv = bi[t]; a0 = a1 = a2 = a3 = bv; }
        else         { a0 = a1 = a2 = a3 = 0.f; }
        GEMVP(gPK + 0 * 16384, Xst, kh * 16, kh * 16 + 16, a0, a1, a2, a3);
        if (kh == 1) {
#pragma unroll
            for (int j = 128; j < 131; j++) {
                float w = __ldg(Wi + j * 128 + t);
                a0 = fmaf(w, Xst[j * 4 + 0], a0);
                a1 = fmaf(w, Xst[j * 4 + 1], a1);
                a2 = fmaf(w, Xst[j * 4 + 2], a2);
                a3 = fmaf(w, Xst[j * 4 + 3], a3);
            }
        }
        *(float4*)(Ps + kh * 512 + t * 4) = make_float4(a0, a1, a2, a3);
    }
    __syncthreads();
    if (kh == 0) {
        float4 p0 = *(const float4*)(Ps + t * 4);
        float4 p1 = *(const float4*)(Ps + 512 + t * 4);
        *(float4*)(Hst + t * 4) = make_float4(
            fmaxf(p0.x + p1.x, 0.f), fmaxf(p0.y + p1.y, 0.f),
            fmaxf(p0.z + p1.z, 0.f), fmaxf(p0.w + p1.w, 0.f));
    }
    __syncthreads();

    // --- L2, L3 ---
#pragma unroll
    for (int l = 0; l < 2; l++) {
        float a0, a1, a2, a3;
        if (kh == 0) { float bv = bh[l * 128 + t]; a0 = a1 = a2 = a3 = bv; }
        else         { a0 = a1 = a2 = a3 = 0.f; }
        GEMVP(gPK + (1 + l) * 16384, Hst + l * 512, kh * 16, kh * 16 + 16, a0, a1, a2, a3);
        *(float4*)(Ps + kh * 512 + t * 4) = make_float4(a0, a1, a2, a3);
        __syncthreads();
        if (kh == 0) {
            float4 p0 = *(const float4*)(Ps + t * 4);
            float4 p1 = *(const float4*)(Ps + 512 + t * 4);
            *(float4*)(Hst + (l + 1) * 512 + t * 4) = make_float4(
                fmaxf(p0.x + p1.x, 0.f), fmaxf(p0.y + p1.y, 0.f),
                fmaxf(p0.z + p1.z, 0.f), fmaxf(p0.w + p1.w, 0.f));
        }
        __syncthreads();
        if (l == 0) ZCHUNK(1);
    }

    // --- L4 + val partials + u4 init (h4 never stored) ---
    {
        float a0, a1, a2, a3;
        if (kh == 0) { float bv = bh[2 * 128 + t]; a0 = a1 = a2 = a3 = bv; }
        else         { a0 = a1 = a2 = a3 = 0.f; }
        GEMVP(gPK + 3 * 16384, Hst + 2 * 512, kh * 16, kh * 16 + 16, a0, a1, a2, a3);
        *(float4*)(Ps + kh * 512 + t * 4) = make_float4(a0, a1, a2, a3);
    }
    __syncthreads();
    if (kh == 0) {
        float4 p0 = *(const float4*)(Ps + t * 4);
        float4 p1 = *(const float4*)(Ps + 512 + t * 4);
        float a0 = p0.x + p1.x, a1 = p0.y + p1.y, a2 = p0.z + p1.z, a3 = p0.w + p1.w;
        float wf_t = Wf[t];
        float4 ov;
        ov.x = (a0 > 0.f) ? wf_t : 0.f;
        ov.y = (a1 > 0.f) ? wf_t : 0.f;
        ov.z = (a2 > 0.f) ? wf_t : 0.f;
        ov.w = (a3 > 0.f) ? wf_t : 0.f;
        *(float4*)(Ua + t * 4) = ov;

        float q0 = fmaxf(a0, 0.f) * wf_t;
        float q1 = fmaxf(a1, 0.f) * wf_t;
        float q2 = fmaxf(a2, 0.f) * wf_t;
        float q3 = fmaxf(a3, 0.f) * wf_t;
#pragma unroll
        for (int o = 16; o > 0; o >>= 1) {
            q0 += __shfl_down_sync(0xffffffffu, q0, o);
            q1 += __shfl_down_sync(0xffffffffu, q1, o);
            q2 += __shfl_down_sync(0xffffffffu, q2, o);
            q3 += __shfl_down_sync(0xffffffffu, q3, o);
        }
        if (lane == 0) *(float4*)(valP + wid * 4) = make_float4(q0, q1, q2, q3);
    }
    __syncthreads();
    ZCHUNK(2);

    // --- backward: B3 (m6), B2 (m5), B1 (m4) — packed transposed matrices ---
#pragma unroll
    for (int s = 0; s < 3; s++) {
        const float* PB = gPK + (6 - s) * 16384;
        const float* Uin  = (s == 1) ? Ub : Ua;
        float*       Uout = (s == 1) ? Ua : Ub;
        const float* Hm = Hst + (2 - s) * 512;
        float a0 = 0.f, a1 = 0.f, a2 = 0.f, a3 = 0.f;
        GEMVP(PB, Uin, kh * 16, kh * 16 + 16, a0, a1, a2, a3);
        *(float4*)(Ps + kh * 512 + t * 4) = make_float4(a0, a1, a2, a3);
        __syncthreads();
        if (kh == 0) {
            float4 p0 = *(const float4*)(Ps + t * 4);
            float4 p1 = *(const float4*)(Ps + 512 + t * 4);
            float4 hm = *(const float4*)(Hm + t * 4);
            float4 ov;
            ov.x = (hm.x > 0.f) ? (p0.x + p1.x) : 0.f;
            ov.y = (hm.y > 0.f) ? (p0.y + p1.y) : 0.f;
            ov.z = (hm.z > 0.f) ? (p0.z + p1.z) : 0.f;
            ov.w = (hm.w > 0.f) ? (p0.w + p1.w) : 0.f;
            *(float4*)(Uout + t * 4) = ov;
        }
        __syncthreads();
        if (s == 0) ZCHUNK(3);
    }

    // --- final: g[j] = sum_k Wi[j*128+k] * u1[k] via packed m7; u1 in Ub ---
    {
        float g0 = 0.f, g1 = 0.f, g2 = 0.f, g3 = 0.f;
        GEMVP(gPK + 7 * 16384, Ub, kh * 16, kh * 16 + 16, g0, g1, g2, g3);
        *(float4*)(Ps + kh * 512 + t * 4) = make_float4(g0, g1, g2, g3);
    }
    __syncthreads();

    if (kh == 0) {
        int j = t;
        float4 p0 = *(const float4*)(Ps + t * 4);
        float4 p1 = *(const float4*)(Ps + 512 + t * 4);
        float g[4] = {p0.x + p1.x, p0.y + p1.y, p0.z + p1.z, p0.w + p1.w};

        if (j >= 4) {
#pragma unroll
            for (int e = 0; e < TB; e++) {
                int gb = b0 + e;
                o_d1f[(size_t)gb * 128 + (j - 3)] = g[e];
            }
        } else if (j == 0) {
#pragma unroll
            for (int e = 0; e < TB; e++) {
                int gb = b0 + e;
                float val = valP[0 * 4 + e] + valP[1 * 4 + e]
                          + valP[2 * 4 + e] + valP[3 * 4 + e] + bf[0];
                float s = sS[e], c = cS[e];
                float gg = g[e];
                float d1c = gg * s;
                float h00 = gg * c * (s - 1e-10f);   // g0 * c * exp(-ft0)
                o_d1c[gb] = d1c;
                o_d2c[gb] = 0.f;
                o_coeffs[gb] = val;
                o_res[gb] = fmaf(d1c, xsS[e] - c, val);
                o_d1f[(size_t)gb * 128] = -h00;
                *(float4*)(o_d2f + (size_t)gb * 16384) = make_float4(h00, 0.f, 0.f, 0.f);
            }
        } else {  // j = 1..3
#pragma unroll
            for (int e = 0; e < TB; e++) {
                int gb = b0 + e;
                o_d1o[(size_t)gb * 3 + (j - 1)] = g[e];
            }
        }
    } else if (t < 3) {
        // extra input rows j=128..130 -> d1f[125..127]  (raw Wi, contiguous)
        int j2 = 128 + t;
        float q0 = 0.f, q1 = 0.f, q2 = 0.f, q3 = 0.f;
#pragma unroll 8
        for (int k = 0; k < 128; k++) {
            float w = __ldg(Wi + j2 * 128 + k);
            float4 uv = *(const float4*)(Ub + k * 4);
            q0 = fmaf(w, uv.x, q0);
            q1 = fmaf(w, uv.y, q1);
            q2 = fmaf(w, uv.z, q2);
            q3 = fmaf(w, uv.w, q3);
        }
        float qe[4] = {q0, q1, q2, q3};
#pragma unroll
        for (int e = 0; e < TB; e++) {
            int gb = b0 + e;
            o_d1f[(size_t)gb * 128 + 125 + t] = qe[e];
        }
    }

    // d2o zeros (4 examples x 9)
    if (tid >= 128 && tid < 128 + TB * 9) {
        int r = tid - 128;
        int b = r / 9, k9 = r % 9;
        o_d2o[(size_t)(b0 + b) * 9 + k9] = 0.f;
    }
}

extern "C" void kernel_launch(void* const* d_in, const int* in_sizes, int n_in,
                              void* d_out, int out_size)
{
    (void)out_size;
    const float *centers = 0, *eps = 0, *dk = 0, *Wi = 0, *Wh = 0, *bh = 0, *bf = 0;
    const void* p2048[2] = {0, 0};
    const float* p128[2] = {0, 0};
    int n2 = 0, n1 = 0;
    for (int i = 0; i < n_in; i++) {
        switch (in_sizes[i]) {
            case 8192:   centers = (const float*)d_in[i]; break;  // (2048,4)
            case 128000: eps     = (const float*)d_in[i]; break;  // (1000,128)
            case 256000: dk      = (const float*)d_in[i]; break;  // (1000,256)
            case 16768:  Wi      = (const float*)d_in[i]; break;  // (131,128)
            case 49152:  Wh      = (const float*)d_in[i]; break;  // (3,128,128)
            case 384:    bh      = (const float*)d_in[i]; break;  // (3,128)
            case 1:      bf      = (const float*)d_in[i]; break;  // (1,)
            case 2048:   if (n2 < 2) p2048[n2++] = d_in[i]; break; // indecies / xs
            case 128:    if (n1 < 2) p128[n1++] = (const float*)d_in[i]; break; // bi / Wf
            default: break;
        }
    }
    const int B = 2048;
    float* out = (float*)d_out;
    float* o_res    = out;
    float* o_fmean  = out + B;
    float* o_flog   = o_fmean + (size_t)B * 128;
    float* o_coeffs = o_flog + (size_t)B * 128;
    float* o_d1c    = o_coeffs + B;
    float* o_d2c    = o_d1c + B;
    float* o_d1o    = o_d2c + B;
    float* o_d2o    = o_d1o + (size_t)B * 3;
    float* o_d1f    = o_d2o + (size_t)B * 9;
    float* o_d2f    = o_d1f + (size_t)B * 128;

    k_pack<<<512, 256>>>(Wh, Wi);
    fused_kernel<<<NBLK, NTHR>>>(
        centers, eps, dk, Wi, Wh, bh, bf,
        p2048[0], p2048[1], p128[0], p128[1],
        o_res, o_fmean, o_flog, o_coeffs, o_d1c, o_d2c, o_d1o, o_d2o, o_d1f, o_d2f);
}